// round 9
// baseline (speedup 1.0000x reference)
#include <cuda_runtime.h>
#include <math.h>
#include <stdint.h>

#define Bq 8
#define Mq 2048
#define Dq 1024
#define Fq 2048
#define Nq 32
#define Pq 4
#define Sq 128   // N*P slots
#define KV 8     // split-K factor for xs stage
#define MSP 4    // M-split for dispatch softmax

// ---------------- scratch (device globals; no allocation allowed) ----------
__device__ float g_logits[Bq * Mq * Sq];        // 8 MB   (B,M,S)
__device__ float g_dispatch[Bq * Mq * Sq];      // 8 MB   (B,M,S)  tf32-rounded
__device__ float g_combine[Bq * Mq * Sq];       // 8 MB   (B,M,S)  tf32-rounded
__device__ float g_xs[Bq * Sq * Dq];            // 4 MB   (B,S,D)  tf32-rounded
__device__ float g_xs_part[KV * Bq * Sq * Dq];  // 32 MB  (KV,B,S,D); reused for ffn partials
__device__ float g_h[Bq * Sq * Fq];             // 8 MB   (B,S,F)  tf32-rounded
__device__ float g_y[Bq * Sq * Dq];             // 4 MB   (B,S,D)
__device__ float g_dmx[MSP * Bq * Sq];          // partial max
__device__ float g_dsum[MSP * Bq * Sq];         // partial sum

// float -> tf32 (round-to-nearest) kept in a 32-bit register
__device__ __forceinline__ uint32_t f2tf32(float f) {
    uint32_t r;
    asm("cvt.rna.tf32.f32 %0, %1;" : "=r"(r) : "f"(f));
    return r;
}
__device__ __forceinline__ float round_tf32(float f) {
    return __uint_as_float(f2tf32(f));
}

__device__ __forceinline__ uint32_t smem_u32(const void* p) {
    return (uint32_t)__cvta_generic_to_shared(p);
}
__device__ __forceinline__ void cp16(uint32_t dst, const void* src) {
    asm volatile("cp.async.cg.shared.global [%0], [%1], 16;" :: "r"(dst), "l"(src));
}
__device__ __forceinline__ void cp_commit() {
    asm volatile("cp.async.commit_group;");
}
template <int N>
__device__ __forceinline__ void cp_wait() {
    asm volatile("cp.async.wait_group %0;" :: "n"(N));
}

// ---- MMA on one K=16 chunk. B fragments always raw bits (HW truncates to tf32).
// A fragments: CVTA ? cvt.rna : raw bits (for pre-rounded intermediates).

// A stored k-major: As[k][m], row stride AST (mod 32 == 8 for no conflicts)
template <int MT, int NT, int AST, int BST, bool CVTA>
__device__ __forceinline__ void mma_akm(const float* __restrict__ As,
                                        const float* __restrict__ Bs,
                                        int mbase, int nbase, float (*acc)[NT][4]) {
    int lane = threadIdx.x & 31;
    int g = lane >> 2, tg = lane & 3;
#pragma unroll
    for (int ks = 0; ks < 2; ks++) {
        uint32_t a[MT][4], b[NT][2];
#pragma unroll
        for (int i = 0; i < MT; i++) {
            const float* p = As + (ks * 8 + tg) * AST + mbase + i * 16 + g;
            if (CVTA) {
                a[i][0] = f2tf32(p[0]);
                a[i][1] = f2tf32(p[8]);
                a[i][2] = f2tf32(p[4 * AST]);
                a[i][3] = f2tf32(p[4 * AST + 8]);
            } else {
                a[i][0] = __float_as_uint(p[0]);
                a[i][1] = __float_as_uint(p[8]);
                a[i][2] = __float_as_uint(p[4 * AST]);
                a[i][3] = __float_as_uint(p[4 * AST + 8]);
            }
        }
#pragma unroll
        for (int j = 0; j < NT; j++) {
            const uint32_t* p = (const uint32_t*)Bs + (ks * 8 + tg) * BST + nbase + j * 8 + g;
            b[j][0] = p[0];
            b[j][1] = p[4 * BST];
        }
#pragma unroll
        for (int i = 0; i < MT; i++)
#pragma unroll
            for (int j = 0; j < NT; j++)
                asm volatile(
                    "mma.sync.aligned.m16n8k8.row.col.f32.tf32.tf32.f32 "
                    "{%0,%1,%2,%3},{%4,%5,%6,%7},{%8,%9},{%0,%1,%2,%3};\n"
                    : "+f"(acc[i][j][0]), "+f"(acc[i][j][1]),
                      "+f"(acc[i][j][2]), "+f"(acc[i][j][3])
                    : "r"(a[i][0]), "r"(a[i][1]), "r"(a[i][2]), "r"(a[i][3]),
                      "r"(b[j][0]), "r"(b[j][1]));
    }
}

// A stored m-major: As[m][k], row stride AST=20 (g*20+tg distinct mod 32)
template <int MT, int NT, int AST, int BST, bool CVTA>
__device__ __forceinline__ void mma_amk(const float* __restrict__ As,
                                        const float* __restrict__ Bs,
                                        int mbase, int nbase, float (*acc)[NT][4]) {
    int lane = threadIdx.x & 31;
    int g = lane >> 2, tg = lane & 3;
#pragma unroll
    for (int ks = 0; ks < 2; ks++) {
        uint32_t a[MT][4], b[NT][2];
#pragma unroll
        for (int i = 0; i < MT; i++) {
            const float* p = As + (size_t)(mbase + i * 16 + g) * AST + ks * 8 + tg;
            if (CVTA) {
                a[i][0] = f2tf32(p[0]);
                a[i][1] = f2tf32(p[8 * AST]);
                a[i][2] = f2tf32(p[4]);
                a[i][3] = f2tf32(p[8 * AST + 4]);
            } else {
                a[i][0] = __float_as_uint(p[0]);
                a[i][1] = __float_as_uint(p[8 * AST]);
                a[i][2] = __float_as_uint(p[4]);
                a[i][3] = __float_as_uint(p[8 * AST + 4]);
            }
        }
#pragma unroll
        for (int j = 0; j < NT; j++) {
            const uint32_t* p = (const uint32_t*)Bs + (ks * 8 + tg) * BST + nbase + j * 8 + g;
            b[j][0] = p[0];
            b[j][1] = p[4 * BST];
        }
#pragma unroll
        for (int i = 0; i < MT; i++)
#pragma unroll
            for (int j = 0; j < NT; j++)
                asm volatile(
                    "mma.sync.aligned.m16n8k8.row.col.f32.tf32.tf32.f32 "
                    "{%0,%1,%2,%3},{%4,%5,%6,%7},{%8,%9},{%0,%1,%2,%3};\n"
                    : "+f"(acc[i][j][0]), "+f"(acc[i][j][1]),
                      "+f"(acc[i][j][2]), "+f"(acc[i][j][3])
                    : "r"(a[i][0]), "r"(a[i][1]), "r"(a[i][2]), "r"(a[i][3]),
                      "r"(b[j][0]), "r"(b[j][1]));
    }
}

// ============ 1) logits + fused combine-softmax ============================
#define LG_A (64 * 20)
#define LG_B (16 * 136)
__global__ void __launch_bounds__(256) logits_mma(const float* __restrict__ x,
                                                  const float* __restrict__ phi) {
    const int r0 = blockIdx.x * 64;
    __shared__ float Sbuf[3 * LG_A + 3 * LG_B];
    float* As = Sbuf;            // [3][64*20]
    float* Bs = Sbuf + 3 * LG_A; // [3][16*136]

    int tid = threadIdx.x, warp = tid >> 5, lane = tid & 31;
    int mbase = (warp >> 2) * 32, nbase = (warp & 3) * 32;
    float acc[2][4][4] = {};

    const float* xb = x + (size_t)r0 * Dq;
    const int NC = Dq / 16;  // 64

    auto issue = [&](int c) {
        int k0 = c * 16, st = c % 3;
        {
            int row = tid >> 2, kc = (tid & 3) * 4;
            cp16(smem_u32(&As[st * LG_A + row * 20 + kc]), &xb[(size_t)row * Dq + k0 + kc]);
        }
#pragma unroll
        for (int u = 0; u < 2; u++) {
            int idx = tid + u * 256;
            int kk = idx >> 5, sc = (idx & 31) * 4;
            cp16(smem_u32(&Bs[st * LG_B + kk * 136 + sc]), &phi[(size_t)(k0 + kk) * Sq + sc]);
        }
        cp_commit();
    };
    issue(0); issue(1);
#pragma unroll 1
    for (int c = 0; c < NC; c++) {
        cp_wait<1>();
        __syncthreads();
        if (c + 2 < NC) issue(c + 2); else cp_commit();
        mma_amk<2, 4, 20, 136, true>(&As[(c % 3) * LG_A], &Bs[(c % 3) * LG_B],
                                     mbase, nbase, acc);
    }

    float (*L)[132] = (float(*)[132])Sbuf;
    int g = lane >> 2, tg = lane & 3;
    float* lb = g_logits + (size_t)r0 * Sq;
    __syncthreads();
#pragma unroll
    for (int i = 0; i < 2; i++)
#pragma unroll
        for (int j = 0; j < 4; j++) {
            int row = mbase + i * 16 + g, col = nbase + j * 8 + tg * 2;
            float2 lo = make_float2(acc[i][j][0], acc[i][j][1]);
            float2 hi = make_float2(acc[i][j][2], acc[i][j][3]);
            *(float2*)&L[row][col] = lo;
            *(float2*)&L[row + 8][col] = hi;
            *(float2*)&lb[(size_t)row * Sq + col] = lo;
            *(float2*)&lb[(size_t)(row + 8) * Sq + col] = hi;
        }
    __syncthreads();

#pragma unroll 1
    for (int q = 0; q < 8; q++) {
        int row = warp * 8 + q;
        float v[4];
        float mx = -1e30f;
#pragma unroll
        for (int j = 0; j < 4; j++) {
            v[j] = L[row][lane + j * 32];
            mx = fmaxf(mx, v[j]);
        }
#pragma unroll
        for (int off = 16; off > 0; off >>= 1)
            mx = fmaxf(mx, __shfl_xor_sync(0xffffffffu, mx, off));
        float e[4], sum = 0.f;
#pragma unroll
        for (int j = 0; j < 4; j++) {
            e[j] = expf(v[j] - mx);
            sum += e[j];
        }
#pragma unroll
        for (int off = 16; off > 0; off >>= 1)
            sum += __shfl_xor_sync(0xffffffffu, sum, off);
        float inv = 1.f / sum;
        float* cp = g_combine + (size_t)(r0 + row) * Sq;
#pragma unroll
        for (int j = 0; j < 4; j++) cp[lane + j * 32] = round_tf32(e[j] * inv);
    }
}

// ============ 2a) dispatch partials ========================================
__global__ void dispatch_part() {
    int b = blockIdx.y, ch = blockIdx.z;
    int s = blockIdx.x * 32 + threadIdx.x;
    int tx = threadIdx.x, ty = threadIdx.y;
    const float* lp = g_logits + ((size_t)b * Mq + ch * (Mq / MSP)) * Sq + s;

    float v[16];
#pragma unroll
    for (int i = 0; i < 16; i++) v[i] = lp[(size_t)(ty + i * 32) * Sq];
    float mx = v[0];
#pragma unroll
    for (int i = 1; i < 16; i++) mx = fmaxf(mx, v[i]);
    float sum = 0.f;
#pragma unroll
    for (int i = 0; i < 16; i++) sum += expf(v[i] - mx);

    __shared__ float rm[32][33], rs[32][33];
    rm[ty][tx] = mx;
    rs[ty][tx] = sum;
    __syncthreads();
    for (int off = 16; off > 0; off >>= 1) {
        if (ty < off) {
            float m1 = rm[ty][tx], s1 = rs[ty][tx];
            float m2 = rm[ty + off][tx], s2 = rs[ty + off][tx];
            float m = fmaxf(m1, m2);
            rm[ty][tx] = m;
            rs[ty][tx] = s1 * expf(m1 - m) + s2 * expf(m2 - m);
        }
        __syncthreads();
    }
    if (ty == 0) {
        g_dmx[(ch * Bq + b) * Sq + s] = rm[0][tx];
        g_dsum[(ch * Bq + b) * Sq + s] = rs[0][tx];
    }
}

// ============ 2b) dispatch write ===========================================
__global__ void dispatch_write() {
    int b = blockIdx.y, ch = blockIdx.z;
    int s = blockIdx.x * 32 + threadIdx.x;
    int ty = threadIdx.y;

    float mx = g_dmx[(0 * Bq + b) * Sq + s];
    float sum = g_dsum[(0 * Bq + b) * Sq + s];
#pragma unroll
    for (int c = 1; c < MSP; c++) {
        float m2 = g_dmx[(c * Bq + b) * Sq + s];
        float s2 = g_dsum[(c * Bq + b) * Sq + s];
        float m = fmaxf(mx, m2);
        sum = sum * expf(mx - m) + s2 * expf(m2 - m);
        mx = m;
    }
    float inv = 1.f / sum;

    const float* lp = g_logits + ((size_t)b * Mq + ch * (Mq / MSP)) * Sq + s;
    float* dp = g_dispatch + ((size_t)b * Mq + ch * (Mq / MSP)) * Sq + s;
#pragma unroll
    for (int i = 0; i < 16; i++) {
        size_t off = (size_t)(ty + i * 32) * Sq;
        dp[off] = round_tf32(expf(lp[off] - mx) * inv);
    }
}

// ============ 3) xs partials, split-K over M ===============================
__global__ void __launch_bounds__(512) xs_mma(const float* __restrict__ x) {
    const int b = blockIdx.z >> 3;
    const int kv = blockIdx.z & 7;
    const int d0 = blockIdx.x * 128;
    const int mk = kv * (Mq / KV);
    __shared__ float As[3][16 * 136];
    __shared__ float Bs[3][16 * 136];

    int tid = threadIdx.x, warp = tid >> 5, lane = tid & 31;
    int mbase = (warp >> 2) * 32, nbase = (warp & 3) * 32;
    float acc[2][4][4] = {};

    const int NC = (Mq / KV) / 16;  // 16

    auto issue = [&](int c) {
        int k0 = mk + c * 16, st = c % 3;
        int kk = tid >> 5, cc = (tid & 31) * 4;
        cp16(smem_u32(&As[st][kk * 136 + cc]),
             &g_dispatch[((size_t)b * Mq + k0 + kk) * Sq + cc]);
        cp16(smem_u32(&Bs[st][kk * 136 + cc]),
             &x[((size_t)b * Mq + k0 + kk) * Dq + d0 + cc]);
        cp_commit();
    };
    issue(0); issue(1);
#pragma unroll 1
    for (int c = 0; c < NC; c++) {
        cp_wait<1>();
        __syncthreads();
        if (c + 2 < NC) issue(c + 2); else cp_commit();
        mma_akm<2, 4, 136, 136, false>(As[c % 3], Bs[c % 3], mbase, nbase, acc);
    }

    int g = lane >> 2, tg = lane & 3;
    float* pp = g_xs_part + ((size_t)kv * Bq + b) * Sq * Dq;
#pragma unroll
    for (int i = 0; i < 2; i++)
#pragma unroll
        for (int j = 0; j < 4; j++) {
            int row = mbase + i * 16 + g, col = d0 + nbase + j * 8 + tg * 2;
            *(float2*)&pp[(size_t)row * Dq + col] = make_float2(acc[i][j][0], acc[i][j][1]);
            *(float2*)&pp[(size_t)(row + 8) * Dq + col] = make_float2(acc[i][j][2], acc[i][j][3]);
        }
}

// ============ 3b) xs = sum_kv partials (tf32-rounded) ======================
__global__ void __launch_bounds__(256) xs_reduce() {
    int i = blockIdx.x * 256 + threadIdx.x;  // float4 index
    const int stride = Bq * Sq * Dq / 4;
    const float4* p = (const float4*)g_xs_part;
    float4 a = p[i];
    float sx = a.x, sy = a.y, sz = a.z, sw = a.w;
#pragma unroll
    for (int c = 1; c < KV; c++) {
        float4 v = p[i + c * stride];
        sx += v.x; sy += v.y; sz += v.z; sw += v.w;
    }
    ((float4*)g_xs)[i] = make_float4(round_tf32(sx), round_tf32(sy),
                                     round_tf32(sz), round_tf32(sw));
}

// ============ 4a) ffn1 split-K partials: xs @ w1 (no bias yet) =============
// BM=32 BN=128, block 128 (warps 1x4, MT=2 NT=4). 4-stage.
// grid (Fq/128, Nq, 2) = (16, 32, 2). Each sk handles half of K=Dq.
__global__ void __launch_bounds__(128) ffn1_sk(const float* __restrict__ w1) {
    const int n = blockIdx.y;
    const int f0 = blockIdx.x * 128;
    const int sk = blockIdx.z;
    const int kbase = sk * (Dq / 2);
    __shared__ float As[4][32 * 20];
    __shared__ float Bs[4][16 * 136];

    int tid = threadIdx.x, warp = tid >> 5, lane = tid & 31;
    int nbase = warp * 32;
    float acc[2][4][4] = {};

    const int NC = (Dq / 2) / 16;  // 32

    auto issue = [&](int c) {
        int k0 = kbase + c * 16, st = c & 3;
        {
            int row = tid >> 2, kc = (tid & 3) * 4;
            cp16(smem_u32(&As[st][row * 20 + kc]),
                 &g_xs[(((size_t)(row >> 2)) * Sq + n * 4 + (row & 3)) * Dq + k0 + kc]);
        }
#pragma unroll
        for (int u = 0; u < 4; u++) {
            int idx = tid + u * 128;
            int kk = idx >> 5, fc = (idx & 31) * 4;
            cp16(smem_u32(&Bs[st][kk * 136 + fc]),
                 &w1[((size_t)n * Dq + k0 + kk) * Fq + f0 + fc]);
        }
        cp_commit();
    };
    issue(0); issue(1); issue(2);
#pragma unroll 1
    for (int c = 0; c < NC; c++) {
        cp_wait<2>();
        __syncthreads();
        if (c + 3 < NC) issue(c + 3); else cp_commit();
        mma_amk<2, 4, 20, 136, false>(As[c & 3], Bs[c & 3], 0, nbase, acc);
    }

    int g = lane >> 2, tg = lane & 3;
    float* pp = g_xs_part + (size_t)sk * (Bq * Sq * Fq);
#pragma unroll
    for (int i = 0; i < 2; i++)
#pragma unroll
        for (int j = 0; j < 4; j++) {
            int row = i * 16 + g;
            int col = nbase + j * 8 + tg * 2;
#pragma unroll
            for (int half = 0; half < 2; half++) {
                int rr = row + half * 8;
                float* hp = &pp[(((size_t)(rr >> 2)) * Sq + n * 4 + (rr & 3)) * Fq + f0 + col];
                *(float2*)hp = make_float2(acc[i][j][half * 2 + 0], acc[i][j][half * 2 + 1]);
            }
        }
}

// ============ 4b) ffn1 reduce: h = round(relu(p0+p1+b1)^2) =================
__global__ void __launch_bounds__(256) ffn1_reduce(const float* __restrict__ b1) {
    int i = blockIdx.x * 256 + threadIdx.x;  // float4 index over B*S*F
    const int stride = Bq * Sq * Fq / 4;
    const float4* p = (const float4*)g_xs_part;
    float4 a = p[i];
    float4 b = p[i + stride];
    int f = (i & (Fq / 4 - 1)) * 4;
    int s = (i / (Fq / 4)) & (Sq - 1);
    int n = s >> 2;
    const float* bp = &b1[(size_t)n * Fq + f];
    float h0 = fmaxf(a.x + b.x + bp[0], 0.f);
    float h1 = fmaxf(a.y + b.y + bp[1], 0.f);
    float h2 = fmaxf(a.z + b.z + bp[2], 0.f);
    float h3 = fmaxf(a.w + b.w + bp[3], 0.f);
    ((float4*)g_h)[i] = make_float4(round_tf32(h0 * h0), round_tf32(h1 * h1),
                                    round_tf32(h2 * h2), round_tf32(h3 * h3));
}

// ============ 5a) ffn2 split-K partials: h @ w2 (no bias yet) ==============
// BM=32 BN=128, block 128 (warps 1x4, MT=2 NT=4). 4-stage.
// grid (Dq/128, Nq, 2) = (8, 32, 2). Each sk handles half of K=Fq.
__global__ void __launch_bounds__(128) ffn2_sk(const float* __restrict__ w2) {
    const int n = blockIdx.y;
    const int d0 = blockIdx.x * 128;
    const int sk = blockIdx.z;
    const int kbase = sk * (Fq / 2);
    __shared__ float As[4][32 * 20];
    __shared__ float Bs[4][16 * 136];

    int tid = threadIdx.x, warp = tid >> 5, lane = tid & 31;
    int nbase = warp * 32;
    float acc[2][4][4] = {};

    const int NC = (Fq / 2) / 16;  // 64

    auto issue = [&](int c) {
        int k0 = kbase + c * 16, st = c & 3;
        {
            int row = tid >> 2, kc = (tid & 3) * 4;
            cp16(smem_u32(&As[st][row * 20 + kc]),
                 &g_h[(((size_t)(row >> 2)) * Sq + n * 4 + (row & 3)) * Fq + k0 + kc]);
        }
#pragma unroll
        for (int u = 0; u < 4; u++) {
            int idx = tid + u * 128;
            int kk = idx >> 5, dc = (idx & 31) * 4;
            cp16(smem_u32(&Bs[st][kk * 136 + dc]),
                 &w2[((size_t)n * Fq + k0 + kk) * Dq + d0 + dc]);
        }
        cp_commit();
    };
    issue(0); issue(1); issue(2);
#pragma unroll 1
    for (int c = 0; c < NC; c++) {
        cp_wait<2>();
        __syncthreads();
        if (c + 3 < NC) issue(c + 3); else cp_commit();
        mma_amk<2, 4, 20, 136, false>(As[c & 3], Bs[c & 3], 0, nbase, acc);
    }

    int g = lane >> 2, tg = lane & 3;
    float* pp = g_xs_part + (size_t)sk * (Bq * Sq * Dq);
#pragma unroll
    for (int i = 0; i < 2; i++)
#pragma unroll
        for (int j = 0; j < 4; j++) {
            int row = i * 16 + g;
            int col = nbase + j * 8 + tg * 2;
#pragma unroll
            for (int half = 0; half < 2; half++) {
                int rr = row + half * 8;
                float* yp = &pp[(((size_t)(rr >> 2)) * Sq + n * 4 + (rr & 3)) * Dq + d0 + col];
                *(float2*)yp = make_float2(acc[i][j][half * 2 + 0], acc[i][j][half * 2 + 1]);
            }
        }
}

// ============ 5b) ffn2 reduce: y = p0 + p1 + b2 ============================
__global__ void __launch_bounds__(256) ffn2_reduce(const float* __restrict__ b2) {
    int i = blockIdx.x * 256 + threadIdx.x;  // float4 index over B*S*D
    const int stride = Bq * Sq * Dq / 4;
    const float4* p = (const float4*)g_xs_part;
    float4 a = p[i];
    float4 b = p[i + stride];
    int d = (i & (Dq / 4 - 1)) * 4;
    int s = (i / (Dq / 4)) & (Sq - 1);
    int n = s >> 2;
    const float* bp = &b2[(size_t)n * Dq + d];
    ((float4*)g_y)[i] = make_float4(a.x + b.x + bp[0], a.y + b.y + bp[1],
                                    a.z + b.z + bp[2], a.w + b.w + bp[3]);
}

// ============ 6) out[b,m,d] = sum_s combine[b,m,s] * y[b,s,d] ==============
__global__ void __launch_bounds__(512) out_mma(float* __restrict__ out) {
    const int b = blockIdx.z;
    const int m0 = blockIdx.y * 128;
    const int d0 = blockIdx.x * 128;
    __shared__ float As[3][128 * 20];
    __shared__ float Bs[3][16 * 136];

    int tid = threadIdx.x, warp = tid >> 5, lane = tid & 31;
    int mbase = (warp >> 2) * 32, nbase = (warp & 3) * 32;
    float acc[2][4][4] = {};

    const float* cb = g_combine + ((size_t)b * Mq + m0) * Sq;
    const int NC = Sq / 16;  // 8

    auto issue = [&](int c) {
        int k0 = c * 16, st = c % 3;
        {
            int row = tid >> 2, kc = (tid & 3) * 4;
            cp16(smem_u32(&As[st][row * 20 + kc]), &cb[(size_t)row * Sq + k0 + kc]);
        }
        {
            int kk = tid >> 5, dc = (tid & 31) * 4;
            cp16(smem_u32(&Bs[st][kk * 136 + dc]),
                 &g_y[((size_t)b * Sq + k0 + kk) * Dq + d0 + dc]);
        }
        cp_commit();
    };
    issue(0); issue(1);
#pragma unroll 1
    for (int c = 0; c < NC; c++) {
        cp_wait<1>();
        __syncthreads();
        if (c + 2 < NC) issue(c + 2); else cp_commit();
        mma_amk<2, 4, 20, 136, false>(As[c % 3], Bs[c % 3], mbase, nbase, acc);
    }

    int g = lane >> 2, tg = lane & 3;
    float* ob = out + ((size_t)b * Mq + m0) * Dq + d0;
#pragma unroll
    for (int i = 0; i < 2; i++)
#pragma unroll
        for (int j = 0; j < 4; j++) {
            int row = mbase + i * 16 + g, col = nbase + j * 8 + tg * 2;
            *(float2*)&ob[(size_t)row * Dq + col] = make_float2(acc[i][j][0], acc[i][j][1]);
            *(float2*)&ob[(size_t)(row + 8) * Dq + col] = make_float2(acc[i][j][2], acc[i][j][3]);
        }
}

// ---------------------------------------------------------------------------
extern "C" void kernel_launch(void* const* d_in, const int* in_sizes, int n_in,
                              void* d_out, int out_size) {
    const float* x   = (const float*)d_in[0];
    const float* phi = (const float*)d_in[1];
    const float* w1  = (const float*)d_in[2];
    const float* b1  = (const float*)d_in[3];
    const float* w2  = (const float*)d_in[4];
    const float* b2  = (const float*)d_in[5];
    float* out = (float*)d_out;

    logits_mma<<<(Bq * Mq) / 64, 256>>>(x, phi);
    dispatch_part<<<dim3(Sq / 32, Bq, MSP), dim3(32, 32)>>>();
    dispatch_write<<<dim3(Sq / 32, Bq, MSP), dim3(32, 32)>>>();
    xs_mma<<<dim3(Dq / 128, 1, Bq * KV), 512>>>(x);
    xs_reduce<<<(Bq * Sq * Dq / 4) / 256, 256>>>();
    ffn1_sk<<<dim3(Fq / 128, Nq, 2), 128>>>(w1);
    ffn1_reduce<<<(Bq * Sq * Fq / 4) / 256, 256>>>(b1);
    ffn2_sk<<<dim3(Dq / 128, Nq, 2), 128>>>(w2);
    ffn2_reduce<<<(Bq * Sq * Dq / 4) / 256, 256>>>(b2);
    out_mma<<<dim3(Dq / 128, Mq / 128, Bq), 512>>>(out);
}

// round 10
// speedup vs baseline: 1.0306x; 1.0306x over previous
#include <cuda_runtime.h>
#include <math.h>
#include <stdint.h>

#define Bq 8
#define Mq 2048
#define Dq 1024
#define Fq 2048
#define Nq 32
#define Pq 4
#define Sq 128   // N*P slots
#define KV 4     // split-K factor for xs stage
#define MSP 4    // M-split for dispatch softmax

// ---------------- scratch (device globals; no allocation allowed) ----------
__device__ float g_logits[Bq * Mq * Sq];        // 8 MB   (B,M,S)
__device__ float g_dispatch[Bq * Mq * Sq];      // 8 MB   (B,M,S)  tf32-rounded
__device__ float g_combine[Bq * Mq * Sq];       // 8 MB   (B,M,S)  tf32-rounded
__device__ float g_xs[Bq * Sq * Dq];            // 4 MB   (B,S,D)  tf32-rounded
__device__ float g_xs_part[KV * Bq * Sq * Dq];  // 16 MB  (KV,B,S,D)
__device__ float g_h[Bq * Sq * Fq];             // 8 MB   (B,S,F)  tf32-rounded
__device__ float g_y[Bq * Sq * Dq];             // 4 MB   (B,S,D)
__device__ float g_dmx[MSP * Bq * Sq];          // partial max
__device__ float g_dsum[MSP * Bq * Sq];         // partial sum

// float -> tf32 (round-to-nearest) kept in a 32-bit register
__device__ __forceinline__ uint32_t f2tf32(float f) {
    uint32_t r;
    asm("cvt.rna.tf32.f32 %0, %1;" : "=r"(r) : "f"(f));
    return r;
}
__device__ __forceinline__ float round_tf32(float f) {
    return __uint_as_float(f2tf32(f));
}

__device__ __forceinline__ uint32_t smem_u32(const void* p) {
    return (uint32_t)__cvta_generic_to_shared(p);
}
__device__ __forceinline__ void cp16(uint32_t dst, const void* src) {
    asm volatile("cp.async.cg.shared.global [%0], [%1], 16;" :: "r"(dst), "l"(src));
}
__device__ __forceinline__ void cp_commit() {
    asm volatile("cp.async.commit_group;");
}
template <int N>
__device__ __forceinline__ void cp_wait() {
    asm volatile("cp.async.wait_group %0;" :: "n"(N));
}

// ---- MMA on one K=16 chunk. B fragments always raw bits (HW truncates to tf32).
// A fragments: CVTA ? cvt.rna : raw bits (for pre-rounded intermediates).

// A stored k-major: As[k][m], row stride AST (mod 32 == 8 for no conflicts)
template <int MT, int NT, int AST, int BST, bool CVTA>
__device__ __forceinline__ void mma_akm(const float* __restrict__ As,
                                        const float* __restrict__ Bs,
                                        int mbase, int nbase, float (*acc)[NT][4]) {
    int lane = threadIdx.x & 31;
    int g = lane >> 2, tg = lane & 3;
#pragma unroll
    for (int ks = 0; ks < 2; ks++) {
        uint32_t a[MT][4], b[NT][2];
#pragma unroll
        for (int i = 0; i < MT; i++) {
            const float* p = As + (ks * 8 + tg) * AST + mbase + i * 16 + g;
            if (CVTA) {
                a[i][0] = f2tf32(p[0]);
                a[i][1] = f2tf32(p[8]);
                a[i][2] = f2tf32(p[4 * AST]);
                a[i][3] = f2tf32(p[4 * AST + 8]);
            } else {
                a[i][0] = __float_as_uint(p[0]);
                a[i][1] = __float_as_uint(p[8]);
                a[i][2] = __float_as_uint(p[4 * AST]);
                a[i][3] = __float_as_uint(p[4 * AST + 8]);
            }
        }
#pragma unroll
        for (int j = 0; j < NT; j++) {
            const uint32_t* p = (const uint32_t*)Bs + (ks * 8 + tg) * BST + nbase + j * 8 + g;
            b[j][0] = p[0];
            b[j][1] = p[4 * BST];
        }
#pragma unroll
        for (int i = 0; i < MT; i++)
#pragma unroll
            for (int j = 0; j < NT; j++)
                asm volatile(
                    "mma.sync.aligned.m16n8k8.row.col.f32.tf32.tf32.f32 "
                    "{%0,%1,%2,%3},{%4,%5,%6,%7},{%8,%9},{%0,%1,%2,%3};\n"
                    : "+f"(acc[i][j][0]), "+f"(acc[i][j][1]),
                      "+f"(acc[i][j][2]), "+f"(acc[i][j][3])
                    : "r"(a[i][0]), "r"(a[i][1]), "r"(a[i][2]), "r"(a[i][3]),
                      "r"(b[j][0]), "r"(b[j][1]));
    }
}

// A stored m-major: As[m][k], row stride AST=20 (g*20+tg distinct mod 32)
template <int MT, int NT, int AST, int BST, bool CVTA>
__device__ __forceinline__ void mma_amk(const float* __restrict__ As,
                                        const float* __restrict__ Bs,
                                        int mbase, int nbase, float (*acc)[NT][4]) {
    int lane = threadIdx.x & 31;
    int g = lane >> 2, tg = lane & 3;
#pragma unroll
    for (int ks = 0; ks < 2; ks++) {
        uint32_t a[MT][4], b[NT][2];
#pragma unroll
        for (int i = 0; i < MT; i++) {
            const float* p = As + (size_t)(mbase + i * 16 + g) * AST + ks * 8 + tg;
            if (CVTA) {
                a[i][0] = f2tf32(p[0]);
                a[i][1] = f2tf32(p[8 * AST]);
                a[i][2] = f2tf32(p[4]);
                a[i][3] = f2tf32(p[8 * AST + 4]);
            } else {
                a[i][0] = __float_as_uint(p[0]);
                a[i][1] = __float_as_uint(p[8 * AST]);
                a[i][2] = __float_as_uint(p[4]);
                a[i][3] = __float_as_uint(p[8 * AST + 4]);
            }
        }
#pragma unroll
        for (int j = 0; j < NT; j++) {
            const uint32_t* p = (const uint32_t*)Bs + (ks * 8 + tg) * BST + nbase + j * 8 + g;
            b[j][0] = p[0];
            b[j][1] = p[4 * BST];
        }
#pragma unroll
        for (int i = 0; i < MT; i++)
#pragma unroll
            for (int j = 0; j < NT; j++)
                asm volatile(
                    "mma.sync.aligned.m16n8k8.row.col.f32.tf32.tf32.f32 "
                    "{%0,%1,%2,%3},{%4,%5,%6,%7},{%8,%9},{%0,%1,%2,%3};\n"
                    : "+f"(acc[i][j][0]), "+f"(acc[i][j][1]),
                      "+f"(acc[i][j][2]), "+f"(acc[i][j][3])
                    : "r"(a[i][0]), "r"(a[i][1]), "r"(a[i][2]), "r"(a[i][3]),
                      "r"(b[j][0]), "r"(b[j][1]));
    }
}

// ============ 1) logits + fused combine-softmax ============================
// rows r = b*M+m. BM=64, BN=128 (all slots). block 256 (warps 2x4, MT=2 NT=4).
// 3-stage cp.async, single sync per chunk.
#define LG_A (64 * 20)
#define LG_B (16 * 136)
__global__ void __launch_bounds__(256) logits_mma(const float* __restrict__ x,
                                                  const float* __restrict__ phi) {
    const int r0 = blockIdx.x * 64;
    __shared__ float Sbuf[3 * LG_A + 3 * LG_B];
    float* As = Sbuf;            // [3][64*20]
    float* Bs = Sbuf + 3 * LG_A; // [3][16*136]

    int tid = threadIdx.x, warp = tid >> 5, lane = tid & 31;
    int mbase = (warp >> 2) * 32, nbase = (warp & 3) * 32;
    float acc[2][4][4] = {};

    const float* xb = x + (size_t)r0 * Dq;
    const int NC = Dq / 16;  // 64

    auto issue = [&](int c) {
        int k0 = c * 16, st = c % 3;
        {
            int row = tid >> 2, kc = (tid & 3) * 4;
            cp16(smem_u32(&As[st * LG_A + row * 20 + kc]), &xb[(size_t)row * Dq + k0 + kc]);
        }
#pragma unroll
        for (int u = 0; u < 2; u++) {
            int idx = tid + u * 256;
            int kk = idx >> 5, sc = (idx & 31) * 4;
            cp16(smem_u32(&Bs[st * LG_B + kk * 136 + sc]), &phi[(size_t)(k0 + kk) * Sq + sc]);
        }
        cp_commit();
    };
    issue(0); issue(1);
#pragma unroll 1
    for (int c = 0; c < NC; c++) {
        cp_wait<1>();
        __syncthreads();
        if (c + 2 < NC) issue(c + 2); else cp_commit();
        mma_amk<2, 4, 20, 136, true>(&As[(c % 3) * LG_A], &Bs[(c % 3) * LG_B],
                                     mbase, nbase, acc);
    }

    // epilogue: stash logits in smem overlay + write raw logits to global
    float (*L)[132] = (float(*)[132])Sbuf;
    int g = lane >> 2, tg = lane & 3;
    float* lb = g_logits + (size_t)r0 * Sq;
    __syncthreads();
#pragma unroll
    for (int i = 0; i < 2; i++)
#pragma unroll
        for (int j = 0; j < 4; j++) {
            int row = mbase + i * 16 + g, col = nbase + j * 8 + tg * 2;
            float2 lo = make_float2(acc[i][j][0], acc[i][j][1]);
            float2 hi = make_float2(acc[i][j][2], acc[i][j][3]);
            *(float2*)&L[row][col] = lo;
            *(float2*)&L[row + 8][col] = hi;
            *(float2*)&lb[(size_t)row * Sq + col] = lo;
            *(float2*)&lb[(size_t)(row + 8) * Sq + col] = hi;
        }
    __syncthreads();

    // row softmax over S=128: each warp handles 8 rows
#pragma unroll 1
    for (int q = 0; q < 8; q++) {
        int row = warp * 8 + q;
        float v[4];
        float mx = -1e30f;
#pragma unroll
        for (int j = 0; j < 4; j++) {
            v[j] = L[row][lane + j * 32];
            mx = fmaxf(mx, v[j]);
        }
#pragma unroll
        for (int off = 16; off > 0; off >>= 1)
            mx = fmaxf(mx, __shfl_xor_sync(0xffffffffu, mx, off));
        float e[4], sum = 0.f;
#pragma unroll
        for (int j = 0; j < 4; j++) {
            e[j] = expf(v[j] - mx);
            sum += e[j];
        }
#pragma unroll
        for (int off = 16; off > 0; off >>= 1)
            sum += __shfl_xor_sync(0xffffffffu, sum, off);
        float inv = 1.f / sum;
        float* cp = g_combine + (size_t)(r0 + row) * Sq;
#pragma unroll
        for (int j = 0; j < 4; j++) cp[lane + j * 32] = round_tf32(e[j] * inv);
    }
}

// ============ 2a) dispatch partials: (max, sum) over M-chunk per (b,s) =====
__global__ void dispatch_part() {
    int b = blockIdx.y, ch = blockIdx.z;
    int s = blockIdx.x * 32 + threadIdx.x;
    int tx = threadIdx.x, ty = threadIdx.y;
    const float* lp = g_logits + ((size_t)b * Mq + ch * (Mq / MSP)) * Sq + s;

    float v[16];
#pragma unroll
    for (int i = 0; i < 16; i++) v[i] = lp[(size_t)(ty + i * 32) * Sq];
    float mx = v[0];
#pragma unroll
    for (int i = 1; i < 16; i++) mx = fmaxf(mx, v[i]);
    float sum = 0.f;
#pragma unroll
    for (int i = 0; i < 16; i++) sum += expf(v[i] - mx);

    __shared__ float rm[32][33], rs[32][33];
    rm[ty][tx] = mx;
    rs[ty][tx] = sum;
    __syncthreads();
    for (int off = 16; off > 0; off >>= 1) {
        if (ty < off) {
            float m1 = rm[ty][tx], s1 = rs[ty][tx];
            float m2 = rm[ty + off][tx], s2 = rs[ty + off][tx];
            float m = fmaxf(m1, m2);
            rm[ty][tx] = m;
            rs[ty][tx] = s1 * expf(m1 - m) + s2 * expf(m2 - m);
        }
        __syncthreads();
    }
    if (ty == 0) {
        g_dmx[(ch * Bq + b) * Sq + s] = rm[0][tx];
        g_dsum[(ch * Bq + b) * Sq + s] = rs[0][tx];
    }
}

// ============ 2b) dispatch write: combine partials + normalize =============
__global__ void dispatch_write() {
    int b = blockIdx.y, ch = blockIdx.z;
    int s = blockIdx.x * 32 + threadIdx.x;
    int ty = threadIdx.y;

    float mx = g_dmx[(0 * Bq + b) * Sq + s];
    float sum = g_dsum[(0 * Bq + b) * Sq + s];
#pragma unroll
    for (int c = 1; c < MSP; c++) {
        float m2 = g_dmx[(c * Bq + b) * Sq + s];
        float s2 = g_dsum[(c * Bq + b) * Sq + s];
        float m = fmaxf(mx, m2);
        sum = sum * expf(mx - m) + s2 * expf(m2 - m);
        mx = m;
    }
    float inv = 1.f / sum;

    const float* lp = g_logits + ((size_t)b * Mq + ch * (Mq / MSP)) * Sq + s;
    float* dp = g_dispatch + ((size_t)b * Mq + ch * (Mq / MSP)) * Sq + s;
#pragma unroll
    for (int i = 0; i < 16; i++) {
        size_t off = (size_t)(ty + i * 32) * Sq;
        dp[off] = round_tf32(expf(lp[off] - mx) * inv);
    }
}

// ============ 3) xs partials, split-K over M ===============================
// BM=128 (ALL slots) BN=128(d), block 512 (warps 4x4, MT=2 NT=4). 3-stage.
// grid (Dq/128, 1, Bq*KV) = (8, 1, 32). NC = 2048/4/16 = 32.
__global__ void __launch_bounds__(512) xs_mma(const float* __restrict__ x) {
    const int b = blockIdx.z >> 2;
    const int kv = blockIdx.z & 3;
    const int d0 = blockIdx.x * 128;
    const int mk = kv * (Mq / KV);
    __shared__ float As[3][16 * 136];
    __shared__ float Bs[3][16 * 136];

    int tid = threadIdx.x, warp = tid >> 5, lane = tid & 31;
    int mbase = (warp >> 2) * 32, nbase = (warp & 3) * 32;
    float acc[2][4][4] = {};

    const int NC = (Mq / KV) / 16;  // 32

    auto issue = [&](int c) {
        int k0 = mk + c * 16, st = c % 3;
        int kk = tid >> 5, cc = (tid & 31) * 4;
        cp16(smem_u32(&As[st][kk * 136 + cc]),
             &g_dispatch[((size_t)b * Mq + k0 + kk) * Sq + cc]);
        cp16(smem_u32(&Bs[st][kk * 136 + cc]),
             &x[((size_t)b * Mq + k0 + kk) * Dq + d0 + cc]);
        cp_commit();
    };
    issue(0); issue(1);
#pragma unroll 1
    for (int c = 0; c < NC; c++) {
        cp_wait<1>();
        __syncthreads();
        if (c + 2 < NC) issue(c + 2); else cp_commit();
        mma_akm<2, 4, 136, 136, false>(As[c % 3], Bs[c % 3], mbase, nbase, acc);
    }

    int g = lane >> 2, tg = lane & 3;
    float* pp = g_xs_part + ((size_t)kv * Bq + b) * Sq * Dq;
#pragma unroll
    for (int i = 0; i < 2; i++)
#pragma unroll
        for (int j = 0; j < 4; j++) {
            int row = mbase + i * 16 + g, col = d0 + nbase + j * 8 + tg * 2;
            *(float2*)&pp[(size_t)row * Dq + col] = make_float2(acc[i][j][0], acc[i][j][1]);
            *(float2*)&pp[(size_t)(row + 8) * Dq + col] = make_float2(acc[i][j][2], acc[i][j][3]);
        }
}

// ============ 3b) xs = sum_kv partials (tf32-rounded) ======================
__global__ void __launch_bounds__(256) xs_reduce() {
    int i = blockIdx.x * 256 + threadIdx.x;  // float4 index
    const int stride = Bq * Sq * Dq / 4;
    const float4* p = (const float4*)g_xs_part;
    float4 a = p[i];
    float sx = a.x, sy = a.y, sz = a.z, sw = a.w;
#pragma unroll
    for (int c = 1; c < KV; c++) {
        float4 v = p[i + c * stride];
        sx += v.x; sy += v.y; sz += v.z; sw += v.w;
    }
    ((float4*)g_xs)[i] = make_float4(round_tf32(sx), round_tf32(sy),
                                     round_tf32(sz), round_tf32(sw));
}

// ============ 4a) h = relu(xs @ w1 + b1)^2 per expert ======================
// BM=32 BN=128, block 128 (warps 1x4, MT=2 NT=4). 4-stage. grid (16, 32).
__global__ void __launch_bounds__(128) ffn1_mma(const float* __restrict__ w1,
                                                const float* __restrict__ b1) {
    const int n = blockIdx.y;
    const int f0 = blockIdx.x * 128;
    __shared__ float As[4][32 * 20];
    __shared__ float Bs[4][16 * 136];

    int tid = threadIdx.x, warp = tid >> 5, lane = tid & 31;
    int nbase = warp * 32;
    float acc[2][4][4] = {};

    const int NC = Dq / 16;  // 64

    auto issue = [&](int c) {
        int k0 = c * 16, st = c & 3;
        {
            int row = tid >> 2, kc = (tid & 3) * 4;
            cp16(smem_u32(&As[st][row * 20 + kc]),
                 &g_xs[(((size_t)(row >> 2)) * Sq + n * 4 + (row & 3)) * Dq + k0 + kc]);
        }
#pragma unroll
        for (int u = 0; u < 4; u++) {
            int idx = tid + u * 128;
            int kk = idx >> 5, fc = (idx & 31) * 4;
            cp16(smem_u32(&Bs[st][kk * 136 + fc]),
                 &w1[((size_t)n * Dq + k0 + kk) * Fq + f0 + fc]);
        }
        cp_commit();
    };
    issue(0); issue(1); issue(2);
#pragma unroll 1
    for (int c = 0; c < NC; c++) {
        cp_wait<2>();
        __syncthreads();
        if (c + 3 < NC) issue(c + 3); else cp_commit();
        mma_amk<2, 4, 20, 136, false>(As[c & 3], Bs[c & 3], 0, nbase, acc);
    }

    int g = lane >> 2, tg = lane & 3;
#pragma unroll
    for (int i = 0; i < 2; i++)
#pragma unroll
        for (int j = 0; j < 4; j++) {
            int row = i * 16 + g;
            int col = nbase + j * 8 + tg * 2;
#pragma unroll
            for (int half = 0; half < 2; half++) {
                int rr = row + half * 8;
                float h0 = acc[i][j][half * 2 + 0] + b1[(size_t)n * Fq + f0 + col];
                float h1 = acc[i][j][half * 2 + 1] + b1[(size_t)n * Fq + f0 + col + 1];
                h0 = fmaxf(h0, 0.f); h1 = fmaxf(h1, 0.f);
                float* hp = &g_h[(((size_t)(rr >> 2)) * Sq + n * 4 + (rr & 3)) * Fq + f0 + col];
                *(float2*)hp = make_float2(round_tf32(h0 * h0), round_tf32(h1 * h1));
            }
        }
}

// ============ 4b) y = h @ w2 + b2 per expert ===============================
// BM=32 BN=128, block 128 (warps 1x4, MT=2 NT=4). 4-stage. grid (8, 32).
__global__ void __launch_bounds__(128) ffn2_mma(const float* __restrict__ w2,
                                                const float* __restrict__ b2) {
    const int n = blockIdx.y;
    const int d0 = blockIdx.x * 128;
    __shared__ float As[4][32 * 20];
    __shared__ float Bs[4][16 * 136];

    int tid = threadIdx.x, warp = tid >> 5, lane = tid & 31;
    int nbase = warp * 32;
    float acc[2][4][4] = {};

    const int NC = Fq / 16;  // 128

    auto issue = [&](int c) {
        int k0 = c * 16, st = c & 3;
        {
            int row = tid >> 2, kc = (tid & 3) * 4;
            cp16(smem_u32(&As[st][row * 20 + kc]),
                 &g_h[(((size_t)(row >> 2)) * Sq + n * 4 + (row & 3)) * Fq + k0 + kc]);
        }
#pragma unroll
        for (int u = 0; u < 4; u++) {
            int idx = tid + u * 128;
            int kk = idx >> 5, dc = (idx & 31) * 4;
            cp16(smem_u32(&Bs[st][kk * 136 + dc]),
                 &w2[((size_t)n * Fq + k0 + kk) * Dq + d0 + dc]);
        }
        cp_commit();
    };
    issue(0); issue(1); issue(2);
#pragma unroll 1
    for (int c = 0; c < NC; c++) {
        cp_wait<2>();
        __syncthreads();
        if (c + 3 < NC) issue(c + 3); else cp_commit();
        mma_amk<2, 4, 20, 136, false>(As[c & 3], Bs[c & 3], 0, nbase, acc);
    }

    int g = lane >> 2, tg = lane & 3;
#pragma unroll
    for (int i = 0; i < 2; i++)
#pragma unroll
        for (int j = 0; j < 4; j++) {
            int row = i * 16 + g;
            int col = nbase + j * 8 + tg * 2;
#pragma unroll
            for (int half = 0; half < 2; half++) {
                int rr = row + half * 8;
                float y0 = acc[i][j][half * 2 + 0] + b2[(size_t)n * Dq + d0 + col];
                float y1 = acc[i][j][half * 2 + 1] + b2[(size_t)n * Dq + d0 + col + 1];
                float* yp = &g_y[(((size_t)(rr >> 2)) * Sq + n * 4 + (rr & 3)) * Dq + d0 + col];
                *(float2*)yp = make_float2(y0, y1);
            }
        }
}

// ============ 5) out[b,m,d] = sum_s combine[b,m,s] * y[b,s,d] ==============
// BM=128(m) BN=128(d), block 512 (warps 4x4, MT=2 NT=4). 3-stage, single sync.
// grid (8, 16, 8). K=S=128.
__global__ void __launch_bounds__(512) out_mma(float* __restrict__ out) {
    const int b = blockIdx.z;
    const int m0 = blockIdx.y * 128;
    const int d0 = blockIdx.x * 128;
    __shared__ float As[3][128 * 20];
    __shared__ float Bs[3][16 * 136];

    int tid = threadIdx.x, warp = tid >> 5, lane = tid & 31;
    int mbase = (warp >> 2) * 32, nbase = (warp & 3) * 32;
    float acc[2][4][4] = {};

    const float* cb = g_combine + ((size_t)b * Mq + m0) * Sq;
    const int NC = Sq / 16;  // 8

    auto issue = [&](int c) {
        int k0 = c * 16, st = c % 3;
        {
            int row = tid >> 2, kc = (tid & 3) * 4;
            cp16(smem_u32(&As[st][row * 20 + kc]), &cb[(size_t)row * Sq + k0 + kc]);
        }
        {
            int kk = tid >> 5, dc = (tid & 31) * 4;
            cp16(smem_u32(&Bs[st][kk * 136 + dc]),
                 &g_y[((size_t)b * Sq + k0 + kk) * Dq + d0 + dc]);
        }
        cp_commit();
    };
    issue(0); issue(1);
#pragma unroll 1
    for (int c = 0; c < NC; c++) {
        cp_wait<1>();
        __syncthreads();
        if (c + 2 < NC) issue(c + 2); else cp_commit();
        mma_amk<2, 4, 20, 136, false>(As[c % 3], Bs[c % 3], mbase, nbase, acc);
    }

    int g = lane >> 2, tg = lane & 3;
    float* ob = out + ((size_t)b * Mq + m0) * Dq + d0;
#pragma unroll
    for (int i = 0; i < 2; i++)
#pragma unroll
        for (int j = 0; j < 4; j++) {
            int row = mbase + i * 16 + g, col = nbase + j * 8 + tg * 2;
            *(float2*)&ob[(size_t)row * Dq + col] = make_float2(acc[i][j][0], acc[i][j][1]);
            *(float2*)&ob[(size_t)(row + 8) * Dq + col] = make_float2(acc[i][j][2], acc[i][j][3]);
        }
}

// ---------------------------------------------------------------------------
extern "C" void kernel_launch(void* const* d_in, const int* in_sizes, int n_in,
                              void* d_out, int out_size) {
    const float* x   = (const float*)d_in[0];
    const float* phi = (const float*)d_in[1];
    const float* w1  = (const float*)d_in[2];
    const float* b1  = (const float*)d_in[3];
    const float* w2  = (const float*)d_in[4];
    const float* b2  = (const float*)d_in[5];
    float* out = (float*)d_out;

    logits_mma<<<(Bq * Mq) / 64, 256>>>(x, phi);
    dispatch_part<<<dim3(Sq / 32, Bq, MSP), dim3(32, 32)>>>();
    dispatch_write<<<dim3(Sq / 32, Bq, MSP), dim3(32, 32)>>>();
    xs_mma<<<dim3(Dq / 128, 1, Bq * KV), 512>>>(x);
    xs_reduce<<<(Bq * Sq * Dq / 4) / 256, 256>>>();
    ffn1_mma<<<dim3(Fq / 128, Nq), 128>>>(w1, b1);
    ffn2_mma<<<dim3(Dq / 128, Nq), 128>>>(w2, b2);
    out_mma<<<dim3(Dq / 128, Mq / 128, Bq), 512>>>(out);
}